// round 6
// baseline (speedup 1.0000x reference)
#include <cuda_runtime.h>
#include <cstdint>

// GPUBatchProcessor v3b: grid-stride with register double-buffering.
// Each thread keeps the NEXT vertex-pair triplet's loads in flight while
// computing/storing the current one -> sustained DRAM pressure instead of
// one-shot burst per thread. batch via blockIdx.y (no integer div).
// (Resubmit — rounds 3-5 hit GPUAcquisitionTimeout; kernel unchanged.)

#define TPB 256
#define PAIRS_PER_THREAD 8   // target iterations per thread (grid sized from this)

__global__ void __launch_bounds__(TPB)
xform_pipe_kernel(const float4* __restrict__ vin,
                  const float*  __restrict__ xforms,   // (B,4,4) row-major
                  float4*       __restrict__ vout,
                  int pairs_per_batch,
                  int stride_pairs)                     // gridDim.x * TPB
{
    __shared__ float sM[16];
    if (threadIdx.x < 16) sM[threadIdx.x] = xforms[blockIdx.y * 16 + threadIdx.x];
    __syncthreads();

    const float m00 = sM[0],  m01 = sM[1],  m02 = sM[2],  m03 = sM[3];
    const float m10 = sM[4],  m11 = sM[5],  m12 = sM[6],  m13 = sM[7];
    const float m20 = sM[8],  m21 = sM[9],  m22 = sM[10], m23 = sM[11];
    const float m30 = sM[12], m31 = sM[13], m32 = sM[14], m33 = sM[15];

    const size_t batch_base = (size_t)blockIdx.y * pairs_per_batch * 3;

    int p = blockIdx.x * TPB + threadIdx.x;
    if (p >= pairs_per_batch) return;

    // prologue: load first triplet
    size_t base = batch_base + (size_t)p * 3;
    float4 A  = __ldcs(&vin[base + 0]);
    float4 Bv = __ldcs(&vin[base + 1]);
    float4 C  = __ldcs(&vin[base + 2]);

    for (;;) {
        // issue NEXT iteration's loads before computing the current one
        int pn = p + stride_pairs;
        bool has_next = pn < pairs_per_batch;
        size_t base_n = batch_base + (size_t)pn * 3;
        float4 An, Bn, Cn;
        if (has_next) {
            An = __ldcs(&vin[base_n + 0]);
            Bn = __ldcs(&vin[base_n + 1]);
            Cn = __ldcs(&vin[base_n + 2]);
        }

        // compute current pair
        float o[12];
        #pragma unroll
        for (int v = 0; v < 2; ++v) {
            float x, y, z, nx, ny, nz;
            if (v == 0) { x = A.x;  y = A.y;  z = A.z; nx = A.w; ny = Bv.x; nz = Bv.y; }
            else        { x = Bv.z; y = Bv.w; z = C.x; nx = C.y; ny = C.z;  nz = C.w; }

            float tw = fmaf(m30, x, fmaf(m31, y, fmaf(m32, z, m33)));
            float iw = 1.0f / tw;
            float px = fmaf(m00, x, fmaf(m01, y, fmaf(m02, z, m03))) * iw;
            float py = fmaf(m10, x, fmaf(m11, y, fmaf(m12, z, m13))) * iw;
            float pz = fmaf(m20, x, fmaf(m21, y, fmaf(m22, z, m23))) * iw;

            float tx = fmaf(m00, nx, fmaf(m01, ny, m02 * nz));
            float ty = fmaf(m10, nx, fmaf(m11, ny, m12 * nz));
            float tz = fmaf(m20, nx, fmaf(m21, ny, m22 * nz));
            float d  = fmaf(tx, tx, fmaf(ty, ty, tz * tz));
            float l  = fmaxf(sqrtf(d), 1e-8f);
            float il = 1.0f / l;

            o[v * 6 + 0] = px;      o[v * 6 + 1] = py;      o[v * 6 + 2] = pz;
            o[v * 6 + 3] = tx * il; o[v * 6 + 4] = ty * il; o[v * 6 + 5] = tz * il;
        }

        __stcs(&vout[base + 0], make_float4(o[0], o[1], o[2],  o[3]));
        __stcs(&vout[base + 1], make_float4(o[4], o[5], o[6],  o[7]));
        __stcs(&vout[base + 2], make_float4(o[8], o[9], o[10], o[11]));

        if (!has_next) break;
        p = pn; base = base_n;
        A = An; Bv = Bn; C = Cn;
    }
}

extern "C" void kernel_launch(void* const* d_in, const int* in_sizes, int n_in,
                              void* d_out, int out_size)
{
    const float4* vin    = (const float4*)d_in[0];     // batch_vertices (B,N,6)
    // d_in[1] = batch_indices — unused by the output
    const float*  xforms = (const float*)d_in[2];      // batch_transforms (B,4,4)

    int n_verts   = in_sizes[0] / 6;        // B*N
    int n_batches = in_sizes[2] / 16;       // B
    int N         = n_verts / n_batches;    // vertices per batch
    int pairs_per_batch = N / 2;            // N even (1e6)

    int grid_x = (pairs_per_batch + TPB * PAIRS_PER_THREAD - 1) / (TPB * PAIRS_PER_THREAD);
    int stride_pairs = grid_x * TPB;

    dim3 grid(grid_x, n_batches);
    xform_pipe_kernel<<<grid, TPB>>>(vin, xforms, (float4*)d_out,
                                     pairs_per_batch, stride_pairs);
}

// round 15
// speedup vs baseline: 1.0677x; 1.0677x over previous
#include <cuda_runtime.h>
#include <cstdint>

// GPUBatchProcessor v4: simplest structure at the DRAM ceiling.
// 1 vertex-pair per thread (3x LDG.128 / 3x STG.128), 2D grid (y=batch, no
// integer div), streaming .cs ops with L2::256B promotion on loads.
// Pipelined v3 regressed (reg pressure); simple + high-occ is the winner shape.
// (Resubmit — rounds 7-14 hit GPUAcquisitionTimeout.)

#define TPB 256

__device__ __forceinline__ float4 ldcs_256(const float4* p) {
    float4 v;
    asm volatile("ld.global.cs.L2::256B.v4.f32 {%0,%1,%2,%3}, [%4];"
                 : "=f"(v.x), "=f"(v.y), "=f"(v.z), "=f"(v.w) : "l"(p));
    return v;
}

__global__ void __launch_bounds__(TPB)
xform_v4_kernel(const float4* __restrict__ vin,
                const float*  __restrict__ xforms,   // (B,4,4) row-major
                float4*       __restrict__ vout,
                int pairs_per_batch)
{
    __shared__ float sM[16];
    if (threadIdx.x < 16) sM[threadIdx.x] = xforms[blockIdx.y * 16 + threadIdx.x];
    __syncthreads();

    int p = blockIdx.x * TPB + threadIdx.x;
    if (p >= pairs_per_batch) return;

    const float m00 = sM[0],  m01 = sM[1],  m02 = sM[2],  m03 = sM[3];
    const float m10 = sM[4],  m11 = sM[5],  m12 = sM[6],  m13 = sM[7];
    const float m20 = sM[8],  m21 = sM[9],  m22 = sM[10], m23 = sM[11];
    const float m30 = sM[12], m31 = sM[13], m32 = sM[14], m33 = sM[15];

    size_t base = (size_t)blockIdx.y * pairs_per_batch * 3 + (size_t)p * 3;

    float4 A  = ldcs_256(&vin[base + 0]);
    float4 Bv = ldcs_256(&vin[base + 1]);
    float4 C  = ldcs_256(&vin[base + 2]);

    float o[12];
    #pragma unroll
    for (int v = 0; v < 2; ++v) {
        float x, y, z, nx, ny, nz;
        if (v == 0) { x = A.x;  y = A.y;  z = A.z; nx = A.w; ny = Bv.x; nz = Bv.y; }
        else        { x = Bv.z; y = Bv.w; z = C.x; nx = C.y; ny = C.z;  nz = C.w; }

        float tw = fmaf(m30, x, fmaf(m31, y, fmaf(m32, z, m33)));
        float iw = 1.0f / tw;
        float px = fmaf(m00, x, fmaf(m01, y, fmaf(m02, z, m03))) * iw;
        float py = fmaf(m10, x, fmaf(m11, y, fmaf(m12, z, m13))) * iw;
        float pz = fmaf(m20, x, fmaf(m21, y, fmaf(m22, z, m23))) * iw;

        float tx = fmaf(m00, nx, fmaf(m01, ny, m02 * nz));
        float ty = fmaf(m10, nx, fmaf(m11, ny, m12 * nz));
        float tz = fmaf(m20, nx, fmaf(m21, ny, m22 * nz));
        float d  = fmaf(tx, tx, fmaf(ty, ty, tz * tz));
        float l  = fmaxf(sqrtf(d), 1e-8f);
        float il = 1.0f / l;

        o[v * 6 + 0] = px;      o[v * 6 + 1] = py;      o[v * 6 + 2] = pz;
        o[v * 6 + 3] = tx * il; o[v * 6 + 4] = ty * il; o[v * 6 + 5] = tz * il;
    }

    __stcs(&vout[base + 0], make_float4(o[0], o[1], o[2],  o[3]));
    __stcs(&vout[base + 1], make_float4(o[4], o[5], o[6],  o[7]));
    __stcs(&vout[base + 2], make_float4(o[8], o[9], o[10], o[11]));
}

extern "C" void kernel_launch(void* const* d_in, const int* in_sizes, int n_in,
                              void* d_out, int out_size)
{
    const float4* vin    = (const float4*)d_in[0];     // batch_vertices (B,N,6)
    // d_in[1] = batch_indices — unused by the output
    const float*  xforms = (const float*)d_in[2];      // batch_transforms (B,4,4)

    int n_verts   = in_sizes[0] / 6;        // B*N
    int n_batches = in_sizes[2] / 16;       // B
    int N         = n_verts / n_batches;    // vertices per batch
    int pairs_per_batch = N / 2;            // N even (1e6)

    dim3 grid((pairs_per_batch + TPB - 1) / TPB, n_batches);
    xform_v4_kernel<<<grid, TPB>>>(vin, xforms, (float4*)d_out, pairs_per_batch);
}